// round 14
// baseline (speedup 1.0000x reference)
#include <cuda_runtime.h>
#include <cuda_fp16.h>
#include <cstdint>

#define DIM 128
#define NPAD 50048
#define NREL 9

// hr messages in fp16: 8 * 50048 * 128 * 2B = 102.5 MB
__device__ __half g_hr_h[(size_t)8 * NPAD * DIM];
// W as fp16 B-fragments: [rel][ks(8)][nt(16)][lane(32)] x uint2 (b0,b1)
__device__ uint2 g_wtf_h[(size_t)NREL * 8 * 16 * 32];

#define NTHREADS 256
#define XBLK 132                       // uint32 per (mt,ks) block (128 + 4 pad)
#define XS_U32 (8 * 8 * XBLK)          // 8448 u32 = 33.8 KB
#define WB_U32 (8 * 16 * 32 * 2)       // 8192 u32 = 32 KB
#define SMEM_BYTES ((XS_U32 + WB_U32) * 4)   // 66560 B

#define MMA_F16(d, a, b)                                                        \
    asm volatile("mma.sync.aligned.m16n8k16.row.col.f32.f16.f16.f32 "          \
                 "{%0,%1,%2,%3}, {%4,%5,%6,%7}, {%8,%9}, {%0,%1,%2,%3};"        \
                 : "+f"((d)[0]), "+f"((d)[1]), "+f"((d)[2]), "+f"((d)[3])       \
                 : "r"((a)[0]), "r"((a)[1]), "r"((a)[2]), "r"((a)[3]),          \
                   "r"((b)[0]), "r"((b)[1]))

__device__ __forceinline__ void cp16(void* s, const void* g) {
    uint32_t sa = (uint32_t)__cvta_generic_to_shared(s);
    asm volatile("cp.async.cg.shared.global [%0], [%1], 16;" :: "r"(sa), "l"(g));
}

// ---------------------------------------------------------------------------
// Prologue: W -> fp16 B fragments for m16n8k16.
// ---------------------------------------------------------------------------
__global__ void conv_w(const float* __restrict__ w, const float* __restrict__ sw) {
    int idx = blockIdx.x * 256 + threadIdx.x;
    if (idx >= NREL * 8 * 16 * 32) return;
    int lane = idx & 31;
    int nt  = (idx >> 5) & 15;
    int ks  = (idx >> 9) & 7;
    int rel = idx >> 12;
    const float* W = (rel < 8) ? (w + (size_t)rel * DIM * DIM) : sw;
    int k0 = ks * 16 + (lane & 3) * 2;
    int n  = nt * 8 + (lane >> 2);
    __half2 b0 = __floats2half2_rn(W[(size_t)k0 * DIM + n],       W[(size_t)(k0 + 1) * DIM + n]);
    __half2 b1 = __floats2half2_rn(W[(size_t)(k0 + 8) * DIM + n], W[(size_t)(k0 + 9) * DIM + n]);
    uint2 o;
    o.x = *(uint32_t*)&b0;
    o.y = *(uint32_t*)&b1;
    g_wtf_h[idx] = o;
}

// ---------------------------------------------------------------------------
// GEMM: grid (nb, 9). One CTA = 128 node rows x ONE relation.
// ---------------------------------------------------------------------------
__global__ void __launch_bounds__(NTHREADS, 2)
rgcn_gemm_mma(const float* __restrict__ x,
              const float* __restrict__ bias,
              float* __restrict__ out,
              int n_nodes) {
    extern __shared__ uint32_t smem[];
    uint32_t* Xs = smem;
    uint32_t* Ws = smem + XS_U32;

    const int tid = threadIdx.x;
    const int wid = tid >> 5, lane = tid & 31;
    const int row0 = blockIdx.x * 128;
    const int rel  = blockIdx.y;
    const int wmt = (wid & 3) * 2;
    const int wnt = (wid >> 2) * 8;

    {
        const uint32_t* src = (const uint32_t*)g_wtf_h + (size_t)rel * WB_U32;
#pragma unroll
        for (int i = tid; i < WB_U32 / 4; i += NTHREADS)
            cp16(Ws + i * 4, src + i * 4);
        asm volatile("cp.async.commit_group;" ::: "memory");
    }

#pragma unroll
    for (int i = tid; i < 128 * 32; i += NTHREADS) {
        int r = i >> 5, c4 = i & 31;
        int node = row0 + r;
        float4 v = (node < n_nodes) ? *(const float4*)(x + (size_t)node * DIM + c4 * 4)
                                    : make_float4(0.f, 0.f, 0.f, 0.f);
        __half2 p0 = __floats2half2_rn(v.x, v.y);
        __half2 p1 = __floats2half2_rn(v.z, v.w);
        int mt = r >> 4, lrr = r & 15;
        int ks = c4 >> 2;
        int lcp = (2 * c4) & 7;
        int lane0 = (lrr & 7) * 4 + (lcp & 3);
        int reg = ((lrr >= 8) ? 1 : 0) + ((lcp >= 4) ? 2 : 0);
        uint32_t* base = Xs + (mt * 8 + ks) * XBLK + reg;
        base[lane0 * 4]       = *(uint32_t*)&p0;
        base[(lane0 + 1) * 4] = *(uint32_t*)&p1;
    }

    asm volatile("cp.async.wait_group 0;" ::: "memory");
    __syncthreads();

    const int lr = lane >> 2;
    const int lc = (lane & 3) * 2;

    float c[16][4];
#pragma unroll
    for (int i = 0; i < 16; i++)
#pragma unroll
        for (int j = 0; j < 4; j++) c[i][j] = 0.0f;

    uint32_t Af[2][2][4];
#pragma unroll
    for (int mt = 0; mt < 2; mt++)
        *(uint4*)Af[0][mt] = *(const uint4*)(Xs + ((wmt + mt) * 8 + 0) * XBLK + lane * 4);

#pragma unroll
    for (int ks = 0; ks < 8; ks++) {
        const int cur = ks & 1, nxt = cur ^ 1;
        uint32_t Bf[8][2];
#pragma unroll
        for (int nt = 0; nt < 8; nt++)
            *(uint2*)Bf[nt] = *(const uint2*)(Ws + ((ks * 16 + wnt + nt) * 32 + lane) * 2);
        if (ks < 7) {
#pragma unroll
            for (int mt = 0; mt < 2; mt++)
                *(uint4*)Af[nxt][mt] =
                    *(const uint4*)(Xs + ((wmt + mt) * 8 + ks + 1) * XBLK + lane * 4);
        }
#pragma unroll
        for (int nt = 0; nt < 8; nt++) {
            MMA_F16(c[nt],     Af[cur][0], Bf[nt]);
            MMA_F16(c[8 + nt], Af[cur][1], Bf[nt]);
        }
    }

    if (rel < 8) {
        __half* base = g_hr_h + ((size_t)rel * NPAD + row0) * DIM;
#pragma unroll
        for (int mt = 0; mt < 2; mt++)
#pragma unroll
            for (int nt = 0; nt < 8; nt++) {
                int r = (wmt + mt) * 16 + lr;
                int cc = (wnt + nt) * 8 + lc;
                *(__half2*)(base + (size_t)r * DIM + cc) =
                    __floats2half2_rn(c[mt * 8 + nt][0], c[mt * 8 + nt][1]);
                *(__half2*)(base + (size_t)(r + 8) * DIM + cc) =
                    __floats2half2_rn(c[mt * 8 + nt][2], c[mt * 8 + nt][3]);
            }
    } else {
#pragma unroll
        for (int mt = 0; mt < 2; mt++)
#pragma unroll
            for (int nt = 0; nt < 8; nt++) {
                int r = (wmt + mt) * 16 + lr;
                int cc = (wnt + nt) * 8 + lc;
                float b0 = bias[cc], b1 = bias[cc + 1];
                int g0 = row0 + r, g1 = row0 + r + 8;
                if (g0 < n_nodes)
                    *(float2*)(out + (size_t)g0 * DIM + cc) =
                        make_float2(c[mt * 8 + nt][0] + b0, c[mt * 8 + nt][1] + b1);
                if (g1 < n_nodes)
                    *(float2*)(out + (size_t)g1 * DIM + cc) =
                        make_float2(c[mt * 8 + nt][2] + b0, c[mt * 8 + nt][3] + b1);
            }
    }
}

// ---------------------------------------------------------------------------
// Phased scatter: one launch per relation. Each warp scans 32 edges, processes
// the ones matching `phase` (gathers confined to one 12.8MB L2-resident slab).
// ---------------------------------------------------------------------------
__device__ __forceinline__ uint2 ldcg8(const void* p) {
    uint2 v;
    asm volatile("ld.global.cg.v2.u32 {%0,%1}, [%2];" : "=r"(v.x), "=r"(v.y) : "l"(p));
    return v;
}

__device__ __forceinline__ void red_edge(float* out, int dst, int lane, uint2 raw) {
    float2 f01 = __half22float2(*(__half2*)&raw.x);
    float2 f23 = __half22float2(*(__half2*)&raw.y);
    float* q = out + (size_t)dst * DIM + lane * 4;
    asm volatile("red.global.add.v4.f32 [%0], {%1, %2, %3, %4};"
                 :: "l"(q), "f"(f01.x), "f"(f01.y), "f"(f23.x), "f"(f23.y)
                 : "memory");
}

__global__ void rgcn_scatter_phase(const int* __restrict__ ei,
                                   const int* __restrict__ et,
                                   float* __restrict__ out,
                                   int n_edges, int phase) {
    int gw = (blockIdx.x * blockDim.x + threadIdx.x) >> 5;
    int lane = threadIdx.x & 31;
    int e = gw * 32 + lane;

    bool match = (e < n_edges) && (et[e] == phase);
    int s = 0, d = 0;
    if (match) { s = ei[e]; d = ei[n_edges + e]; }
    unsigned mask = __ballot_sync(0xffffffffu, match);

    const __half* slab = g_hr_h + (size_t)phase * NPAD * DIM;

    while (mask) {
        int b0 = __ffs(mask) - 1; mask &= mask - 1;
        int b1 = -1;
        if (mask) { b1 = __ffs(mask) - 1; mask &= mask - 1; }

        int s0 = __shfl_sync(0xffffffffu, s, b0);
        int d0 = __shfl_sync(0xffffffffu, d, b0);
        uint2 r0 = ldcg8(slab + (size_t)s0 * DIM + lane * 4);

        if (b1 >= 0) {
            int s1 = __shfl_sync(0xffffffffu, s, b1);
            int d1 = __shfl_sync(0xffffffffu, d, b1);
            uint2 r1 = ldcg8(slab + (size_t)s1 * DIM + lane * 4);
            red_edge(out, d0, lane, r0);
            red_edge(out, d1, lane, r1);
        } else {
            red_edge(out, d0, lane, r0);
        }
    }
}

__global__ void rgcn_relu(float* __restrict__ out, int n4) {
    int i = blockIdx.x * blockDim.x + threadIdx.x;
    if (i < n4) {
        float4 v = ((float4*)out)[i];
        v.x = fmaxf(v.x, 0.0f); v.y = fmaxf(v.y, 0.0f);
        v.z = fmaxf(v.z, 0.0f); v.w = fmaxf(v.w, 0.0f);
        ((float4*)out)[i] = v;
    }
}

// ---------------------------------------------------------------------------
extern "C" void kernel_launch(void* const* d_in, const int* in_sizes, int n_in,
                              void* d_out, int out_size) {
    const float* x    = (const float*)d_in[0];
    const float* w    = (const float*)d_in[1];
    const float* sw   = (const float*)d_in[2];
    const float* bias = (const float*)d_in[3];
    const int* ei = (const int*)d_in[4];
    const int* et = (const int*)d_in[5];

    int n_nodes = in_sizes[0] / DIM;
    int n_edges = in_sizes[5];
    float* out = (float*)d_out;

    cudaFuncSetAttribute(rgcn_gemm_mma, cudaFuncAttributeMaxDynamicSharedMemorySize,
                         SMEM_BYTES);

    int cw = (NREL * 8 * 16 * 32 + 255) / 256;
    conv_w<<<cw, 256>>>(w, sw);

    int nb = (n_nodes + 127) / 128;
    dim3 grid(nb, NREL);
    rgcn_gemm_mma<<<grid, NTHREADS, SMEM_BYTES>>>(x, bias, out, n_nodes);

    int n_warps = (n_edges + 31) / 32;
    int blocks = (n_warps * 32 + 255) / 256;
    for (int p = 0; p < 8; p++)
        rgcn_scatter_phase<<<blocks, 256>>>(ei, et, out, n_edges, p);

    int n4 = n_nodes * DIM / 4;
    rgcn_relu<<<(n4 + 255) / 256, 256>>>(out, n4);
}

// round 15
// speedup vs baseline: 1.2218x; 1.2218x over previous
#include <cuda_runtime.h>
#include <cuda_fp16.h>
#include <cstdint>

#define DIM 128
#define NPAD 50048
#define NREL 9

// hr messages in fp16: 8 * 50048 * 128 * 2B = 102.5 MB
__device__ __half g_hr_h[(size_t)8 * NPAD * DIM];
// W as fp16 B-fragments: [rel][ks(8)][nt(16)][lane(32)] x uint2 (b0,b1)
__device__ uint2 g_wtf_h[(size_t)NREL * 8 * 16 * 32];

#define NTHREADS 256
#define XBLK 132                       // uint32 per (mt,ks) block (128 + 4 pad)
#define XS_U32 (8 * 8 * XBLK)          // 8448 u32 = 33.8 KB
#define WB_U32 (8 * 16 * 32 * 2)       // 8192 u32 = 32 KB
#define SMEM_BYTES ((XS_U32 + WB_U32) * 4)   // 66560 B

#define MMA_F16(d, a, b)                                                        \
    asm volatile("mma.sync.aligned.m16n8k16.row.col.f32.f16.f16.f32 "          \
                 "{%0,%1,%2,%3}, {%4,%5,%6,%7}, {%8,%9}, {%0,%1,%2,%3};"        \
                 : "+f"((d)[0]), "+f"((d)[1]), "+f"((d)[2]), "+f"((d)[3])       \
                 : "r"((a)[0]), "r"((a)[1]), "r"((a)[2]), "r"((a)[3]),          \
                   "r"((b)[0]), "r"((b)[1]))

__device__ __forceinline__ void cp16(void* s, const void* g) {
    uint32_t sa = (uint32_t)__cvta_generic_to_shared(s);
    asm volatile("cp.async.cg.shared.global [%0], [%1], 16;" :: "r"(sa), "l"(g));
}

// streaming (evict-first) 32-bit store: hr data is never re-read by this kernel
__device__ __forceinline__ void stcs32(void* p, uint32_t v) {
    asm volatile("st.global.cs.u32 [%0], %1;" :: "l"(p), "r"(v) : "memory");
}

// ---------------------------------------------------------------------------
// Prologue: W -> fp16 B fragments for m16n8k16.
// ---------------------------------------------------------------------------
__global__ void conv_w(const float* __restrict__ w, const float* __restrict__ sw) {
    int idx = blockIdx.x * 256 + threadIdx.x;
    if (idx >= NREL * 8 * 16 * 32) return;
    int lane = idx & 31;
    int nt  = (idx >> 5) & 15;
    int ks  = (idx >> 9) & 7;
    int rel = idx >> 12;
    const float* W = (rel < 8) ? (w + (size_t)rel * DIM * DIM) : sw;
    int k0 = ks * 16 + (lane & 3) * 2;
    int n  = nt * 8 + (lane >> 2);
    __half2 b0 = __floats2half2_rn(W[(size_t)k0 * DIM + n],       W[(size_t)(k0 + 1) * DIM + n]);
    __half2 b1 = __floats2half2_rn(W[(size_t)(k0 + 8) * DIM + n], W[(size_t)(k0 + 9) * DIM + n]);
    uint2 o;
    o.x = *(uint32_t*)&b0;
    o.y = *(uint32_t*)&b1;
    g_wtf_h[idx] = o;
}

// ---------------------------------------------------------------------------
// GEMM: grid (nb, 9). One CTA = 128 node rows x ONE relation.
// hr stores are streaming (.cs) so X (25.6MB) stays L2-resident for re-reads.
// ---------------------------------------------------------------------------
__global__ void __launch_bounds__(NTHREADS, 2)
rgcn_gemm_mma(const float* __restrict__ x,
              const float* __restrict__ bias,
              float* __restrict__ out,
              int n_nodes) {
    extern __shared__ uint32_t smem[];
    uint32_t* Xs = smem;
    uint32_t* Ws = smem + XS_U32;

    const int tid = threadIdx.x;
    const int wid = tid >> 5, lane = tid & 31;
    const int row0 = blockIdx.x * 128;
    const int rel  = blockIdx.y;
    const int wmt = (wid & 3) * 2;
    const int wnt = (wid >> 2) * 8;

    {
        const uint32_t* src = (const uint32_t*)g_wtf_h + (size_t)rel * WB_U32;
#pragma unroll
        for (int i = tid; i < WB_U32 / 4; i += NTHREADS)
            cp16(Ws + i * 4, src + i * 4);
        asm volatile("cp.async.commit_group;" ::: "memory");
    }

#pragma unroll
    for (int i = tid; i < 128 * 32; i += NTHREADS) {
        int r = i >> 5, c4 = i & 31;
        int node = row0 + r;
        float4 v = (node < n_nodes) ? __ldg((const float4*)(x + (size_t)node * DIM + c4 * 4))
                                    : make_float4(0.f, 0.f, 0.f, 0.f);
        __half2 p0 = __floats2half2_rn(v.x, v.y);
        __half2 p1 = __floats2half2_rn(v.z, v.w);
        int mt = r >> 4, lrr = r & 15;
        int ks = c4 >> 2;
        int lcp = (2 * c4) & 7;
        int lane0 = (lrr & 7) * 4 + (lcp & 3);
        int reg = ((lrr >= 8) ? 1 : 0) + ((lcp >= 4) ? 2 : 0);
        uint32_t* base = Xs + (mt * 8 + ks) * XBLK + reg;
        base[lane0 * 4]       = *(uint32_t*)&p0;
        base[(lane0 + 1) * 4] = *(uint32_t*)&p1;
    }

    asm volatile("cp.async.wait_group 0;" ::: "memory");
    __syncthreads();

    const int lr = lane >> 2;
    const int lc = (lane & 3) * 2;

    float c[16][4];
#pragma unroll
    for (int i = 0; i < 16; i++)
#pragma unroll
        for (int j = 0; j < 4; j++) c[i][j] = 0.0f;

    uint32_t Af[2][2][4];
#pragma unroll
    for (int mt = 0; mt < 2; mt++)
        *(uint4*)Af[0][mt] = *(const uint4*)(Xs + ((wmt + mt) * 8 + 0) * XBLK + lane * 4);

#pragma unroll
    for (int ks = 0; ks < 8; ks++) {
        const int cur = ks & 1, nxt = cur ^ 1;
        uint32_t Bf[8][2];
#pragma unroll
        for (int nt = 0; nt < 8; nt++)
            *(uint2*)Bf[nt] = *(const uint2*)(Ws + ((ks * 16 + wnt + nt) * 32 + lane) * 2);
        if (ks < 7) {
#pragma unroll
            for (int mt = 0; mt < 2; mt++)
                *(uint4*)Af[nxt][mt] =
                    *(const uint4*)(Xs + ((wmt + mt) * 8 + ks + 1) * XBLK + lane * 4);
        }
#pragma unroll
        for (int nt = 0; nt < 8; nt++) {
            MMA_F16(c[nt],     Af[cur][0], Bf[nt]);
            MMA_F16(c[8 + nt], Af[cur][1], Bf[nt]);
        }
    }

    if (rel < 8) {
        __half* base = g_hr_h + ((size_t)rel * NPAD + row0) * DIM;
#pragma unroll
        for (int mt = 0; mt < 2; mt++)
#pragma unroll
            for (int nt = 0; nt < 8; nt++) {
                int r = (wmt + mt) * 16 + lr;
                int cc = (wnt + nt) * 8 + lc;
                __half2 h0 = __floats2half2_rn(c[mt * 8 + nt][0], c[mt * 8 + nt][1]);
                __half2 h1 = __floats2half2_rn(c[mt * 8 + nt][2], c[mt * 8 + nt][3]);
                stcs32(base + (size_t)r * DIM + cc,       *(uint32_t*)&h0);
                stcs32(base + (size_t)(r + 8) * DIM + cc, *(uint32_t*)&h1);
            }
    } else {
#pragma unroll
        for (int mt = 0; mt < 2; mt++)
#pragma unroll
            for (int nt = 0; nt < 8; nt++) {
                int r = (wmt + mt) * 16 + lr;
                int cc = (wnt + nt) * 8 + lc;
                float b0 = bias[cc], b1 = bias[cc + 1];
                int g0 = row0 + r, g1 = row0 + r + 8;
                if (g0 < n_nodes)
                    *(float2*)(out + (size_t)g0 * DIM + cc) =
                        make_float2(c[mt * 8 + nt][0] + b0, c[mt * 8 + nt][1] + b1);
                if (g1 < n_nodes)
                    *(float2*)(out + (size_t)g1 * DIM + cc) =
                        make_float2(c[mt * 8 + nt][2] + b0, c[mt * 8 + nt][3] + b1);
            }
    }
}

// ---------------------------------------------------------------------------
// Scatter (R12 form): 4 edges/warp (MLP=4). Gather 256B fp16 per edge
// (8B/lane via ld.global.cg), convert to fp32, red.v4 into out[dst].
// ---------------------------------------------------------------------------
__device__ __forceinline__ uint2 ldcg8(const void* p) {
    uint2 v;
    asm volatile("ld.global.cg.v2.u32 {%0,%1}, [%2];" : "=r"(v.x), "=r"(v.y) : "l"(p));
    return v;
}

__global__ void rgcn_scatter(const int* __restrict__ ei,
                             const int* __restrict__ et,
                             float* __restrict__ out,
                             int n_edges) {
    int gw = (blockIdx.x * blockDim.x + threadIdx.x) >> 5;
    int lane = threadIdx.x & 31;
    int e0 = gw * 4;
    if (e0 >= n_edges) return;

    int s[4], d[4], r[4];
    int cnt = min(4, n_edges - e0);
#pragma unroll
    for (int j = 0; j < 4; j++) {
        int e = e0 + ((j < cnt) ? j : 0);
        s[j] = ei[e]; d[j] = ei[n_edges + e]; r[j] = et[e];
    }
    uint2 raw[4];
#pragma unroll
    for (int j = 0; j < 4; j++)
        raw[j] = ldcg8(g_hr_h + ((size_t)r[j] * NPAD + (size_t)s[j]) * DIM + lane * 4);
#pragma unroll
    for (int j = 0; j < 4; j++) {
        if (j < cnt) {
            float2 f01 = __half22float2(*(__half2*)&raw[j].x);
            float2 f23 = __half22float2(*(__half2*)&raw[j].y);
            float* q = out + (size_t)d[j] * DIM + lane * 4;
            asm volatile("red.global.add.v4.f32 [%0], {%1, %2, %3, %4};"
                         :: "l"(q), "f"(f01.x), "f"(f01.y), "f"(f23.x), "f"(f23.y)
                         : "memory");
        }
    }
}

__global__ void rgcn_relu(float* __restrict__ out, int n4) {
    int i = blockIdx.x * blockDim.x + threadIdx.x;
    if (i < n4) {
        float4 v = ((float4*)out)[i];
        v.x = fmaxf(v.x, 0.0f); v.y = fmaxf(v.y, 0.0f);
        v.z = fmaxf(v.z, 0.0f); v.w = fmaxf(v.w, 0.0f);
        ((float4*)out)[i] = v;
    }
}

// ---------------------------------------------------------------------------
extern "C" void kernel_launch(void* const* d_in, const int* in_sizes, int n_in,
                              void* d_out, int out_size) {
    const float* x    = (const float*)d_in[0];
    const float* w    = (const float*)d_in[1];
    const float* sw   = (const float*)d_in[2];
    const float* bias = (const float*)d_in[3];
    const int* ei = (const int*)d_in[4];
    const int* et = (const int*)d_in[5];

    int n_nodes = in_sizes[0] / DIM;
    int n_edges = in_sizes[5];
    float* out = (float*)d_out;

    cudaFuncSetAttribute(rgcn_gemm_mma, cudaFuncAttributeMaxDynamicSharedMemorySize,
                         SMEM_BYTES);

    int cw = (NREL * 8 * 16 * 32 + 255) / 256;
    conv_w<<<cw, 256>>>(w, sw);

    int nb = (n_nodes + 127) / 128;
    dim3 grid(nb, NREL);
    rgcn_gemm_mma<<<grid, NTHREADS, SMEM_BYTES>>>(x, bias, out, n_nodes);

    int n_warps = (n_edges + 3) / 4;
    long long total_threads = (long long)n_warps * 32;
    int blocks = (int)((total_threads + 255) / 256);
    rgcn_scatter<<<blocks, 256>>>(ei, et, out, n_edges);

    int n4 = n_nodes * DIM / 4;
    rgcn_relu<<<(n4 + 255) / 256, 256>>>(out, n4);
}